// round 7
// baseline (speedup 1.0000x reference)
#include <cuda_runtime.h>
#include <cstddef>

typedef unsigned long long ull;

#define NTHREADS 256
#define TROWS 128

// ======== transposed-weight global scratch: Wt[j][k] per layer ========
__device__ __align__(16) float g_wt[65536];
__constant__ int c_pre[10]  = {0,4096,8192,12288,18688,25088,31488,52224,61440,65536};
__constant__ int c_nin[9]   = {64,64,64,80,80,80,144,144,64};
__constant__ int c_nout[9]  = {64,64,64,80,80,80,144,64,64};

__global__ void prep_kernel(const float* w0,const float* w1,const float* w2,
                            const float* w3,const float* w4,const float* w5,
                            const float* w6,const float* w7,const float* w8)
{
    const float* W[9] = {w0,w1,w2,w3,w4,w5,w6,w7,w8};
    int i = blockIdx.x * blockDim.x + threadIdx.x;
    if (i >= 65536) return;
    int s = 0;
    while (i >= c_pre[s + 1]) s++;
    int l = i - c_pre[s];
    int nin = c_nin[s], nout = c_nout[s];
    int j = l / nin, k = l - j * nin;
    g_wt[i] = W[s][k * nout + j];
}

// ======== packed fp32x2 + cp.async helpers ========
__device__ __forceinline__ ull ffma2(ull a, ull b, ull c) {
    ull d; asm("fma.rn.f32x2 %0, %1, %2, %3;" : "=l"(d) : "l"(a), "l"(b), "l"(c)); return d;
}
__device__ __forceinline__ float2 u2f(ull a) {
    float2 f; asm("mov.b64 {%0, %1}, %2;" : "=f"(f.x), "=f"(f.y) : "l"(a)); return f;
}
__device__ __forceinline__ float lrelu(float v) { return v > 0.0f ? v : 0.01f * v; }
__device__ __forceinline__ void cpa16(float* dst, const float* src) {
    unsigned sa = (unsigned)__cvta_generic_to_shared(dst);
    asm volatile("cp.async.cg.shared.global [%0], [%1], 16;" :: "r"(sa), "l"(src));
}
#define CPA_COMMIT() asm volatile("cp.async.commit_group;" ::: "memory")
#define CPA_WAIT0()  asm volatile("cp.async.wait_group 0;"  ::: "memory")

// ======== epilogue chunk maps ========
__constant__ int c_kind[31] = {0,0,0,0,0,0,0,0,0,0,0,0,1,1,1,1,0,0,0,1,0,0,0,0,0,1,1,1,1,1,1};
__constant__ int c_A[31]    = {320,152,304,304,304,304,304,152,152,152,152,152,
                               40,41,42,43, 152,208,416, 39, 208,152,416,360,152,
                               44,45,46,47,48,49};
__constant__ int c_B[31]    = {18,20,22,23,24,25,26,27,28,29,30,31,
                               0,2,3,5, 35,36,37, 1, 32,33,34,19,38,
                               4,4,4,4,4,4};
// blob: suit@0(40) rank@40(112) pos@152(56) action@208(96) active@304(16)
//       street@320(40) numpl@360(56) blind@416(16)

// ======== shared layout (floats) ========
#define OFF_BLOB 0                   // 432
#define OFF_SW   432                 // 48
#define OFF_SB   480                 // 48
#define OFF_BIAS 528                 // 704 (ends 1232)
#define OFF_A    1232                // 128*84 = 10752
#define OFF_B    11984               // 128*84 = 10752
#define OFF_C    22736               // 128*148 = 18944
#define OFF_W    41680               // 2 slots * 6720
#define SLOTF    6720
#define SMEM_FLOATS 55120
#define SMEM_BYTES  (SMEM_FLOATS * 4)  // 220480 -> 1 CTA/SM, regs free to 255
// D (144-wide, stride 148) overlays A+B (21504 >= 18944)

// ======== dense (sub-)layer: 4 rows/lane, k-pair FFMA2 ========
// Xs[row][k] stride SIN (>= NIN+4: unguarded x-prefetch is in-bounds);
// Wtg transposed [NJ][NIN]; writes Ys[row][JOFF+j] stride SOUT.
template<int NIN, int SIN, int NJ, int SOUT, int JOFF, int KC, bool ACT>
__device__ __forceinline__ void layer4(const float* __restrict__ Xs, float* __restrict__ Ys,
                                       const float* __restrict__ Wtg,
                                       const float* __restrict__ bsm,
                                       float* __restrict__ Wslots)
{
    const int t = threadIdx.x, L = t & 31, wid = t >> 5;
    constexpr int TILEJ = NJ / 8;
    constexpr int WS  = KC + 4;
    constexpr int NCH = NIN / KC;
    constexpr int PER = KC / 4;
    const int j0 = wid * TILEJ;

    ull acc[TILEJ][4];
    #pragma unroll
    for (int j = 0; j < TILEJ; j++)
        #pragma unroll
        for (int g = 0; g < 4; g++) acc[j][g] = 0ull;

    const float* xr = Xs + L * SIN;

    // stage chunk 0
    for (int i = t; i < NJ * PER; i += NTHREADS) {
        int j = i / PER, k4 = (i - j * PER) << 2;
        cpa16(Wslots + j * WS + k4, Wtg + j * NIN + k4);
    }
    CPA_COMMIT(); CPA_WAIT0();
    __syncthreads();

    #pragma unroll
    for (int c = 0; c < NCH; c++) {
        if (c + 1 < NCH) {
            float* dst = Wslots + ((c + 1) & 1) * SLOTF;
            const float* src = Wtg + (c + 1) * KC;
            for (int i = t; i < NJ * PER; i += NTHREADS) {
                int j = i / PER, k4 = (i - j * PER) << 2;
                cpa16(dst + j * WS + k4, src + j * NIN + k4);
            }
            CPA_COMMIT();
        }
        {
            const float* Wt = Wslots + (c & 1) * SLOTF + j0 * WS;
            const float* xk = xr + c * KC;
            ulonglong2 xc[4];
            #pragma unroll
            for (int g = 0; g < 4; g++)
                xc[g] = *reinterpret_cast<const ulonglong2*>(xk + g * 32 * SIN);
            #pragma unroll 2
            for (int k4 = 0; k4 < PER; k4++) {
                ulonglong2 xn[4];
                #pragma unroll
                for (int g = 0; g < 4; g++)   // prefetch next k4 (pad makes it safe)
                    xn[g] = *reinterpret_cast<const ulonglong2*>(xk + g * 32 * SIN + (k4 + 1) * 4);
                #pragma unroll
                for (int j = 0; j < TILEJ; j++) {
                    ulonglong2 wv = *reinterpret_cast<const ulonglong2*>(Wt + j * WS + k4 * 4);
                    #pragma unroll
                    for (int g = 0; g < 4; g++) {
                        acc[j][g] = ffma2(xc[g].x, wv.x, acc[j][g]);
                        acc[j][g] = ffma2(xc[g].y, wv.y, acc[j][g]);
                    }
                }
                #pragma unroll
                for (int g = 0; g < 4; g++) xc[g] = xn[g];
            }
        }
        if (c + 1 < NCH) { CPA_WAIT0(); __syncthreads(); }
    }

    // epilogue: horizontal add + bias (+act)
    #pragma unroll
    for (int j = 0; j < TILEJ; j += 2) {
        float b0 = bsm[j0 + j], b1 = bsm[j0 + j + 1];
        #pragma unroll
        for (int g = 0; g < 4; g++) {
            float2 s0 = u2f(acc[j][g]);
            float2 s1 = u2f(acc[j + 1][g]);
            float v0 = s0.x + s0.y + b0;
            float v1 = s1.x + s1.y + b1;
            if (ACT) { v0 = lrelu(v0); v1 = lrelu(v1); }
            *reinterpret_cast<float2*>(Ys + (L + 32 * g) * SOUT + JOFF + j0 + j) =
                make_float2(v0, v1);
        }
    }
    __syncthreads();  // Ys visible + weight slots free before next layer stages
}

// final 64->64 layer: no activation, writes out cols [0,64)
__device__ __forceinline__ void layer_final(const float* __restrict__ Xs,
                                            const float* __restrict__ Wtg,
                                            const float* __restrict__ bsm,
                                            float* __restrict__ Wslots,
                                            float* __restrict__ out, size_t g0)
{
    const int t = threadIdx.x, L = t & 31, wid = t >> 5;
    constexpr int WS = 68, PER = 16;
    const int j0 = wid * 8;

    ull acc[8][4];
    #pragma unroll
    for (int j = 0; j < 8; j++)
        #pragma unroll
        for (int g = 0; g < 4; g++) acc[j][g] = 0ull;

    for (int i = t; i < 64 * PER; i += NTHREADS) {
        int j = i / PER, k4 = (i - j * PER) << 2;
        cpa16(Wslots + j * WS + k4, Wtg + j * 64 + k4);
    }
    CPA_COMMIT(); CPA_WAIT0();
    __syncthreads();

    const float* xr = Xs + L * 148;
    const float* Wt = Wslots + j0 * WS;
    ulonglong2 xc[4];
    #pragma unroll
    for (int g = 0; g < 4; g++)
        xc[g] = *reinterpret_cast<const ulonglong2*>(xr + g * 32 * 148);
    #pragma unroll 2
    for (int k4 = 0; k4 < 16; k4++) {
        ulonglong2 xn[4];
        #pragma unroll
        for (int g = 0; g < 4; g++)
            xn[g] = *reinterpret_cast<const ulonglong2*>(xr + g * 32 * 148 + (k4 + 1) * 4);
        #pragma unroll
        for (int j = 0; j < 8; j++) {
            ulonglong2 wv = *reinterpret_cast<const ulonglong2*>(Wt + j * WS + k4 * 4);
            #pragma unroll
            for (int g = 0; g < 4; g++) {
                acc[j][g] = ffma2(xc[g].x, wv.x, acc[j][g]);
                acc[j][g] = ffma2(xc[g].y, wv.y, acc[j][g]);
            }
        }
        #pragma unroll
        for (int g = 0; g < 4; g++) xc[g] = xn[g];
    }

    #pragma unroll
    for (int g = 0; g < 4; g++) {
        float v[8];
        #pragma unroll
        for (int j = 0; j < 8; j++) {
            float2 s = u2f(acc[j][g]);
            v[j] = s.x + s.y + bsm[j0 + j];
        }
        float* op = out + (g0 + L + 32 * g) * 312 + j0;
        *reinterpret_cast<float4*>(op)     = make_float4(v[0], v[1], v[2], v[3]);
        *reinterpret_cast<float4*>(op + 4) = make_float4(v[4], v[5], v[6], v[7]);
    }
}

__global__ void __launch_bounds__(NTHREADS, 1)
preproc_kernel(const float* __restrict__ state,
               const float* __restrict__ suit_emb, const float* __restrict__ rank_emb,
               const float* __restrict__ hb1, const float* __restrict__ hb2,
               const float* __restrict__ hb3, const float* __restrict__ bb1,
               const float* __restrict__ bb2, const float* __restrict__ bb3,
               const float* __restrict__ cb1, const float* __restrict__ cb2,
               const float* __restrict__ cb3,
               const float* __restrict__ pos_emb, const float* __restrict__ action_emb,
               const float* __restrict__ active_emb, const float* __restrict__ street_emb,
               const float* __restrict__ numpl_emb, const float* __restrict__ blind_emb,
               const float* __restrict__ scalar_W, const float* __restrict__ scalar_b,
               float* __restrict__ out)
{
    extern __shared__ float smem[];
    float* blob = smem + OFF_BLOB;
    float* sW   = smem + OFF_SW;
    float* sB   = smem + OFF_SB;
    float* bias = smem + OFF_BIAS;
    float* A    = smem + OFF_A;      // stride 84
    float* Bb   = smem + OFF_B;      // stride 84
    float* C    = smem + OFF_C;      // stride 148
    float* D    = smem + OFF_A;      // stride 148 (overlays A+B)
    float* W    = smem + OFF_W;

    const int t = threadIdx.x;
    const size_t g0 = (size_t)blockIdx.x * TROWS;
    const float* st = state + g0 * 50;

    // ---- stage tables + biases ----
    for (int i = t; i < 40;  i += NTHREADS) blob[0   + i] = suit_emb[i];
    for (int i = t; i < 112; i += NTHREADS) blob[40  + i] = rank_emb[i];
    for (int i = t; i < 56;  i += NTHREADS) blob[152 + i] = pos_emb[i];
    for (int i = t; i < 96;  i += NTHREADS) blob[208 + i] = action_emb[i];
    for (int i = t; i < 16;  i += NTHREADS) blob[304 + i] = active_emb[i];
    for (int i = t; i < 40;  i += NTHREADS) blob[320 + i] = street_emb[i];
    for (int i = t; i < 56;  i += NTHREADS) blob[360 + i] = numpl_emb[i];
    for (int i = t; i < 16;  i += NTHREADS) blob[416 + i] = blind_emb[i];
    for (int i = t; i < 48;  i += NTHREADS) { sW[i] = scalar_W[i]; sB[i] = scalar_b[i]; }
    for (int i = t; i < 64;  i += NTHREADS) bias[0   + i] = hb1[i];
    for (int i = t; i < 64;  i += NTHREADS) bias[64  + i] = hb2[i];
    for (int i = t; i < 64;  i += NTHREADS) bias[128 + i] = hb3[i];
    for (int i = t; i < 80;  i += NTHREADS) bias[192 + i] = bb1[i];
    for (int i = t; i < 80;  i += NTHREADS) bias[272 + i] = bb2[i];
    for (int i = t; i < 80;  i += NTHREADS) bias[352 + i] = bb3[i];
    for (int i = t; i < 144; i += NTHREADS) bias[432 + i] = cb1[i];
    for (int i = t; i < 64;  i += NTHREADS) bias[576 + i] = cb2[i];
    for (int i = t; i < 64;  i += NTHREADS) bias[640 + i] = cb3[i];
    __syncthreads();

    // ---- cheap output columns 64..311 ----
    for (int i = t; i < TROWS * 248; i += NTHREADS) {
        int r = i / 248, cc = i - r * 248;
        int ch = cc >> 3, e = cc & 7;
        int kind = c_kind[ch], Ai = c_A[ch], Bc = c_B[ch];
        float v;
        if (kind == 0) {
            int xi = (int)__ldg(st + r * 50 + Bc);
            v = blob[Ai + xi * 8 + e];
        } else {
            v = __ldg(st + r * 50 + Ai) * sW[Bc * 8 + e] + sB[Bc * 8 + e];
        }
        out[(g0 + r) * 312 + 64 + cc] = v;
    }

    // ---- gather hand input (64 feats) -> A row-major ----
    for (int i = t; i < 64 * TROWS; i += NTHREADS) {
        int r = i & 127, k = i >> 7;
        int c = k >> 4, w = k & 15;
        float v;
        if (w < 8) { int s  = (int)__ldg(st + r * 50 + 2 * c + 1); v = blob[0  + s * 8 + w]; }
        else       { int rk = (int)__ldg(st + r * 50 + 2 * c);     v = blob[40 + rk * 8 + (w - 8)]; }
        A[r * 84 + k] = v;
    }
    // (h1's stage barrier establishes visibility)

    layer4<64, 84, 64, 84,  0,  64, true >(A,  Bb, g_wt + 0,     bias + 0,   W);
    layer4<64, 84, 64, 84,  0,  64, true >(Bb, A,  g_wt + 4096,  bias + 64,  W);
    layer4<64, 84, 64, 148, 0,  64, false>(A,  C,  g_wt + 8192,  bias + 128, W);

    // ---- gather board input (80 feats) -> A (h3's end-barrier cleared WAR) ----
    for (int i = t; i < 80 * TROWS; i += NTHREADS) {
        int r = i & 127, k = i >> 7;
        int c = k >> 4, w = k & 15;
        float v;
        if (w < 8) { int s  = (int)__ldg(st + r * 50 + 9 + 2 * c); v = blob[0  + s * 8 + w]; }
        else       { int rk = (int)__ldg(st + r * 50 + 8 + 2 * c); v = blob[40 + rk * 8 + (w - 8)]; }
        A[r * 84 + k] = v;
    }

    layer4<80, 84, 80, 84,  0,  80, true >(A,  Bb, g_wt + 12288, bias + 192, W);
    layer4<80, 84, 80, 84,  0,  80, true >(Bb, A,  g_wt + 18688, bias + 272, W);
    layer4<80, 84, 80, 148, 64, 80, false>(A,  C,  g_wt + 25088, bias + 352, W);

    // ---- combined MLP: C[144] -> D[144] -> C[0:64) -> out ----
    layer4<144, 148, 80, 148, 0,  72, true>(C, D, g_wt + 31488,         bias + 432, W);
    layer4<144, 148, 64, 148, 80, 72, true>(C, D, g_wt + 31488 + 11520, bias + 512, W);
    layer4<144, 148, 64, 148, 0,  72, true>(D, C, g_wt + 52224,         bias + 576, W);
    layer_final(C, g_wt + 61440, bias + 640, W, out, g0);
}

extern "C" void kernel_launch(void* const* d_in, const int* in_sizes, int n_in,
                              void* d_out, int out_size)
{
    (void)n_in; (void)out_size;
    cudaFuncSetAttribute(preproc_kernel, cudaFuncAttributeMaxDynamicSharedMemorySize, SMEM_BYTES);

    // one-time-per-graph weight transpose into g_wt
    prep_kernel<<<256, 256>>>(
        (const float*)d_in[3],  (const float*)d_in[5],  (const float*)d_in[7],
        (const float*)d_in[9],  (const float*)d_in[11], (const float*)d_in[13],
        (const float*)d_in[15], (const float*)d_in[17], (const float*)d_in[19]);

    const int nrows = in_sizes[0] / 50;     // 262144
    const int grid  = nrows / TROWS;        // 2048

    preproc_kernel<<<grid, NTHREADS, SMEM_BYTES>>>(
        (const float*)d_in[0],
        (const float*)d_in[1],  (const float*)d_in[2],
        (const float*)d_in[4],  (const float*)d_in[6],  (const float*)d_in[8],
        (const float*)d_in[10], (const float*)d_in[12], (const float*)d_in[14],
        (const float*)d_in[16], (const float*)d_in[18], (const float*)d_in[20],
        (const float*)d_in[21], (const float*)d_in[22],
        (const float*)d_in[23], (const float*)d_in[24],
        (const float*)d_in[25], (const float*)d_in[26],
        (const float*)d_in[27], (const float*)d_in[28],
        (float*)d_out);
}